// round 2
// baseline (speedup 1.0000x reference)
#include <cuda_runtime.h>
#include <cuda_bf16.h>

// Problem constants
#define TT 16384
#define HH 100
#define GG 400   // 4*H

// Scratch (device globals: no allocation allowed in kernel_launch)
__device__ float g_xg[TT * GG];   // precomputed input gate contributions [T, 4H]
__device__ float g_hs[TT * HH];   // hidden states [T, H]

// ---------------------------------------------------------------------------
// Packed fp32x2 FMA (Blackwell FFMA2): 2 fp32 FMAs per instruction
// ---------------------------------------------------------------------------
__device__ __forceinline__ float2 ffma2(float2 a, float2 b, float2 c) {
    float2 r;
    asm("fma.rn.f32x2 %0, %1, %2, %3;"
        : "=l"(reinterpret_cast<unsigned long long&>(r))
        : "l"(reinterpret_cast<unsigned long long&>(a)),
          "l"(reinterpret_cast<unsigned long long&>(b)),
          "l"(reinterpret_cast<unsigned long long&>(c)));
    return r;
}
__device__ __forceinline__ float2 fadd2(float2 a, float2 b) {
    float2 r;
    asm("add.rn.f32x2 %0, %1, %2;"
        : "=l"(reinterpret_cast<unsigned long long&>(r))
        : "l"(reinterpret_cast<unsigned long long&>(a)),
          "l"(reinterpret_cast<unsigned long long&>(b)));
    return r;
}

__device__ __forceinline__ float ex2_approx(float x) {
    float r; asm("ex2.approx.f32 %0, %1;" : "=f"(r) : "f"(x)); return r;
}
__device__ __forceinline__ float rcp_approx(float x) {
    float r; asm("rcp.approx.f32 %0, %1;" : "=f"(r) : "f"(x)); return r;
}

#define LOG2E 1.4426950408889634f

// Branch-free activation: A * rcp(1 + ex2(K*g)) + B
// sigmoid: K=-log2e, A=1, B=0       tanh: K=-2log2e, A=2, B=-1
__device__ __forceinline__ float act_f(float g, float K, float A, float B) {
    float e = ex2_approx(K * g);
    float r = rcp_approx(1.0f + e);
    return fmaf(A, r, B);
}

// tanh via same machinery (saturates correctly: ex2(+inf)=inf -> rcp=0 -> -1;
// ex2(-inf)=0 -> rcp(1)=1 -> +1)
__device__ __forceinline__ float tanh_fast(float x) {
    return act_f(x, -2.0f * LOG2E, 2.0f, -1.0f);
}

// ---------------------------------------------------------------------------
// Kernel 1: x_gates[t][j] = b_ih[j] + b_hh[j] + sum_k x[t][k] * W_ih[j][k]
// ---------------------------------------------------------------------------
__global__ void k_xgates(const float* __restrict__ x,
                         const float* __restrict__ Wih,
                         const float* __restrict__ bih,
                         const float* __restrict__ bhh) {
    int idx = blockIdx.x * blockDim.x + threadIdx.x;
    if (idx >= TT * GG) return;
    int t = idx / GG;
    int j = idx - t * GG;
    const float* xr = x + t * 3;
    const float* wr = Wih + j * 3;
    float s = bih[j] + bhh[j];
    s += xr[0] * wr[0] + xr[1] * wr[1] + xr[2] * wr[2];
    g_xg[idx] = s;
}

// ---------------------------------------------------------------------------
// Kernel 2: sequential LSTM. One block, 13 warps (416 threads).
// Warp w, lane l: unit u = 8*w + (l&7), gate = l>>3  (gate order: i,f,g,o)
// Branch-free: every lane computes its gate activation with per-lane
// (K,A,B) constants; every lane shuffles all 4 gates of unit b=l&7 and
// redundantly computes c/h (replicated register state). Only lanes with
// gate==0 && u<100 store. One __syncthreads per step (double-buffered h).
// ---------------------------------------------------------------------------
__global__ void __launch_bounds__(416, 1)
k_lstm_seq(const float* __restrict__ Whh) {
    __shared__ __align__(16) float sh_h[2][104];

    const int tid  = threadIdx.x;
    const int w    = tid >> 5;
    const int l    = tid & 31;
    const int b    = l & 7;
    const int u    = w * 8 + b;
    const int gate = l >> 3;
    const bool do_store = (gate == 0) && (u < HH);
    const int row  = (u < HH) ? (gate * HH + u) : 0;

    // Per-lane activation constants (set once; no divergence in the loop)
    const float Kc = (gate == 2) ? (-2.0f * LOG2E) : (-LOG2E);
    const float Ac = (gate == 2) ? 2.0f : 1.0f;
    const float Bc = (gate == 2) ? -1.0f : 0.0f;

    // Load this thread's W_hh row (100 floats, 8B-aligned) into registers
    float2 wv[50];
    {
        const float2* wr = reinterpret_cast<const float2*>(Whh + row * HH);
        #pragma unroll
        for (int i = 0; i < 50; i++) wv[i] = wr[i];
    }

    // Zero both h buffers
    for (int i = tid; i < 208; i += blockDim.x)
        (&sh_h[0][0])[i] = 0.0f;
    __syncthreads();

    float c = 0.0f;   // replicated across the 4 gate-lanes of unit b

    // 2-deep x_gates prefetch pipeline
    float xg0 = g_xg[row];
    float xg1 = g_xg[GG + row];

    const float4* hpA = reinterpret_cast<const float4*>(&sh_h[0][0]);
    const float4* hpB = reinterpret_cast<const float4*>(&sh_h[1][0]);

    for (int t = 0; t < TT; t++) {
        const float cur = xg0;
        xg0 = xg1;
        const int tn = t + 2;
        xg1 = (tn < TT) ? __ldg(&g_xg[tn * GG + row]) : 0.0f;

        const float4* hp = (t & 1) ? hpB : hpA;
        float* shw = (t & 1) ? &sh_h[0][0] : &sh_h[1][0];

        // 100-MAC dot product: 25 broadcast LDS.128 + 50 packed FMAs,
        // 4 accumulator chains (~13 deep each)
        float2 acc0 = make_float2(cur, 0.0f);
        float2 acc1 = make_float2(0.0f, 0.0f);
        float2 acc2 = make_float2(0.0f, 0.0f);
        float2 acc3 = make_float2(0.0f, 0.0f);
        #pragma unroll
        for (int i = 0; i < 12; i++) {
            float4 h0 = hp[2 * i];
            float4 h1 = hp[2 * i + 1];
            acc0 = ffma2(make_float2(h0.x, h0.y), wv[4 * i],     acc0);
            acc1 = ffma2(make_float2(h0.z, h0.w), wv[4 * i + 1], acc1);
            acc2 = ffma2(make_float2(h1.x, h1.y), wv[4 * i + 2], acc2);
            acc3 = ffma2(make_float2(h1.z, h1.w), wv[4 * i + 3], acc3);
        }
        {
            float4 h0 = hp[24];
            acc0 = ffma2(make_float2(h0.x, h0.y), wv[48], acc0);
            acc1 = ffma2(make_float2(h0.z, h0.w), wv[49], acc1);
        }
        float2 s01 = fadd2(acc0, acc1);
        float2 s23 = fadd2(acc2, acc3);
        float2 s   = fadd2(s01, s23);
        float g = s.x + s.y;

        // Branch-free per-gate activation
        float a = act_f(g, Kc, Ac, Bc);

        // All lanes gather the 4 gate activations of unit b
        float a_i = __shfl_sync(0xffffffffu, a, b);
        float a_f = __shfl_sync(0xffffffffu, a, b + 8);
        float a_g = __shfl_sync(0xffffffffu, a, b + 16);
        float a_o = __shfl_sync(0xffffffffu, a, b + 24);

        // Redundant (replicated) c/h update on every lane — no divergence
        c = fmaf(a_f, c, a_i * a_g);
        float hn = a_o * tanh_fast(c);

        if (do_store) {
            shw[u] = hn;
            g_hs[t * HH + u] = hn;
        }
        __syncthreads();
    }
}

// ---------------------------------------------------------------------------
// Kernel 3: out[t] = sigmoid( hs[t,:] . W_lin + b_lin ).  Warp per row.
// ---------------------------------------------------------------------------
__global__ void k_proj(const float* __restrict__ Wlin,
                       const float* __restrict__ blin,
                       float* __restrict__ out) {
    int gw = (blockIdx.x * blockDim.x + threadIdx.x) >> 5;
    int l  = threadIdx.x & 31;
    if (gw >= TT) return;
    const float* hr = g_hs + gw * HH;
    float s = 0.0f;
    #pragma unroll
    for (int i = 0; i < 4; i++) {
        int k = l + 32 * i;
        if (k < HH) s += hr[k] * Wlin[k];
    }
    #pragma unroll
    for (int off = 16; off; off >>= 1)
        s += __shfl_xor_sync(0xffffffffu, s, off);
    if (l == 0) {
        float z = s + blin[0];
        out[gw] = rcp_approx(1.0f + ex2_approx(-LOG2E * z));
    }
}

// ---------------------------------------------------------------------------
// Launch
// Inputs (metadata order): input_x, W_ih, W_hh, b_ih, b_hh, W_lin, b_lin
// ---------------------------------------------------------------------------
extern "C" void kernel_launch(void* const* d_in, const int* in_sizes, int n_in,
                              void* d_out, int out_size) {
    const float* x    = (const float*)d_in[0];
    const float* Wih  = (const float*)d_in[1];
    const float* Whh  = (const float*)d_in[2];
    const float* bih  = (const float*)d_in[3];
    const float* bhh  = (const float*)d_in[4];
    const float* Wlin = (const float*)d_in[5];
    const float* blin = (const float*)d_in[6];
    float* out = (float*)d_out;

    (void)in_sizes; (void)n_in; (void)out_size;

    {
        int n = TT * GG;
        k_xgates<<<(n + 255) / 256, 256>>>(x, Wih, bih, bhh);
    }
    k_lstm_seq<<<1, 416>>>(Whh);
    {
        int warps = TT;
        int threads = 256;
        int blocks = (warps * 32 + threads - 1) / threads;
        k_proj<<<blocks, threads>>>(Wlin, blin, out);
    }
}

// round 3
// speedup vs baseline: 1.3170x; 1.3170x over previous
#include <cuda_runtime.h>
#include <cuda_bf16.h>

// Problem constants
#define TT 16384
#define HH 100
#define GG 400   // 4*H

// Scratch (device global: no allocation allowed in kernel_launch)
__device__ float g_hs[TT * HH];   // hidden states [T, H]

// ---------------------------------------------------------------------------
// Packed fp32x2 FMA (Blackwell): 2 fp32 FMAs per instruction
// ---------------------------------------------------------------------------
__device__ __forceinline__ float2 ffma2(float2 a, float2 b, float2 c) {
    float2 r;
    asm("fma.rn.f32x2 %0, %1, %2, %3;"
        : "=l"(reinterpret_cast<unsigned long long&>(r))
        : "l"(reinterpret_cast<unsigned long long&>(a)),
          "l"(reinterpret_cast<unsigned long long&>(b)),
          "l"(reinterpret_cast<unsigned long long&>(c)));
    return r;
}

__device__ __forceinline__ float ex2_approx(float x) {
    float r; asm("ex2.approx.f32 %0, %1;" : "=f"(r) : "f"(x)); return r;
}
__device__ __forceinline__ float rcp_approx(float x) {
    float r; asm("rcp.approx.f32 %0, %1;" : "=f"(r) : "f"(x)); return r;
}

#define LOG2E 1.4426950408889634f

// Branch-free activation: A * rcp(1 + ex2(K*g)) + B
// sigmoid: K=-log2e, A=1, B=0   tanh: K=-2log2e, A=2, B=-1
// Saturates correctly at +/-inf preactivation.
__device__ __forceinline__ float act_f(float g, float K, float A, float B) {
    float e = ex2_approx(K * g);
    float r = rcp_approx(1.0f + e);
    return fmaf(A, r, B);
}
__device__ __forceinline__ float tanh_fast(float x) {
    return act_f(x, -2.0f * LOG2E, 2.0f, -1.0f);
}

// ---------------------------------------------------------------------------
// Kernel: sequential LSTM, one block, 13 warps (416 threads).
// Warp w, lane l: unit u = 8*w + (l&7), gate = l>>3 (order: i,f,g,o).
// x (16384x3 floats, 192 KB) preloaded into dynamic SMEM once; per step the
// input-gate contribution is computed on the fly (3 broadcast LDS + 3 FFMA),
// so the loop touches NO global loads. W_hh row lives in registers
// (50 float2), h read via broadcast LDS.128 from a double-buffered SMEM
// array -> exactly one __syncthreads per step.
// ---------------------------------------------------------------------------
__global__ void __launch_bounds__(416, 1)
k_lstm_seq(const float* __restrict__ x,
           const float* __restrict__ Whh,
           const float* __restrict__ Wih,
           const float* __restrict__ bih,
           const float* __restrict__ bhh) {
    extern __shared__ __align__(16) float dynsmem[];
    float* sx = dynsmem;                 // [TT*3] = 49152 floats
    float* sh = dynsmem + TT * 3;        // [2][104] h double buffer (16B aligned)

    const int tid  = threadIdx.x;
    const int w    = tid >> 5;
    const int l    = tid & 31;
    const int b    = l & 7;
    const int u    = w * 8 + b;
    const int gate = l >> 3;
    const bool valid = (u < HH);
    const int row  = valid ? (gate * HH + u) : 0;

    // Per-lane activation constants (uniform per lane across the whole loop)
    const float Kc = (gate == 2) ? (-2.0f * LOG2E) : (-LOG2E);
    const float Ac = (gate == 2) ? 2.0f : 1.0f;
    const float Bc = (gate == 2) ? -1.0f : 0.0f;

    // Preload x into SMEM (coalesced float4)
    {
        const float4* xs = reinterpret_cast<const float4*>(x);
        float4* xd = reinterpret_cast<float4*>(sx);
        const int n4 = TT * 3 / 4;       // 12288
        for (int i = tid; i < n4; i += 416) xd[i] = xs[i];
    }

    // This thread's recurrent weight row -> registers (100 floats)
    float2 wv[50];
    {
        const float2* wr = reinterpret_cast<const float2*>(Whh + row * HH);
        #pragma unroll
        for (int i = 0; i < 50; i++) wv[i] = wr[i];
    }
    // Input weight row (3 floats) + combined bias
    const float wi0 = Wih[row * 3 + 0];
    const float wi1 = Wih[row * 3 + 1];
    const float wi2 = Wih[row * 3 + 2];
    const float bias = bih[row] + bhh[row];

    // Zero both h buffers
    for (int i = tid; i < 208; i += 416) sh[i] = 0.0f;
    __syncthreads();

    float c = 0.0f;
    const float4* hpA = reinterpret_cast<const float4*>(sh);
    const float4* hpB = reinterpret_cast<const float4*>(sh + 104);

    const float* xr = sx;
    for (int t = 0; t < TT; t++, xr += 3) {
        // Input contribution (broadcast LDS, no global traffic)
        float xg = fmaf(wi0, xr[0], bias);
        xg = fmaf(wi1, xr[1], xg);
        xg = fmaf(wi2, xr[2], xg);

        const float4* hp = (t & 1) ? hpB : hpA;
        float* shw = (t & 1) ? (sh) : (sh + 104);

        // 100-MAC dot product: 25 broadcast LDS.128 + 50 packed FMAs,
        // 2 accumulator chains (register-budget-safe, R1-proven)
        float2 acc0 = make_float2(xg, 0.0f);
        float2 acc1 = make_float2(0.0f, 0.0f);
        #pragma unroll
        for (int i = 0; i < 25; i++) {
            float4 hv = hp[i];
            acc0 = ffma2(make_float2(hv.x, hv.y), wv[2 * i],     acc0);
            acc1 = ffma2(make_float2(hv.z, hv.w), wv[2 * i + 1], acc1);
        }
        float g = (acc0.x + acc1.x) + (acc0.y + acc1.y);

        // Branch-free per-gate activation
        float a = act_f(g, Kc, Ac, Bc);

        // Gather the 4 gate activations of this unit within the warp
        float a_f = __shfl_sync(0xffffffffu, a, b + 8);
        float a_g = __shfl_sync(0xffffffffu, a, b + 16);
        float a_o = __shfl_sync(0xffffffffu, a, b + 24);

        if (gate == 0 && valid) {
            // a = i
            c = fmaf(a_f, c, a * a_g);
            float hn = a_o * tanh_fast(c);
            shw[u] = hn;
            g_hs[t * HH + u] = hn;
        }
        __syncthreads();
    }
}

// ---------------------------------------------------------------------------
// Output projection: out[t] = sigmoid( hs[t,:] . W_lin + b_lin ). Warp/row.
// ---------------------------------------------------------------------------
__global__ void k_proj(const float* __restrict__ Wlin,
                       const float* __restrict__ blin,
                       float* __restrict__ out) {
    int gw = (blockIdx.x * blockDim.x + threadIdx.x) >> 5;
    int l  = threadIdx.x & 31;
    if (gw >= TT) return;
    const float* hr = g_hs + gw * HH;
    float s = 0.0f;
    #pragma unroll
    for (int i = 0; i < 4; i++) {
        int k = l + 32 * i;
        if (k < HH) s += hr[k] * Wlin[k];
    }
    #pragma unroll
    for (int off = 16; off; off >>= 1)
        s += __shfl_xor_sync(0xffffffffu, s, off);
    if (l == 0) {
        float z = s + blin[0];
        out[gw] = rcp_approx(1.0f + ex2_approx(-LOG2E * z));
    }
}

// No-op launch-slot filler (to steer ncu's -s 5 onto k_lstm_seq next capture)
__global__ void k_nop() {}

// ---------------------------------------------------------------------------
// Launch.  Inputs: input_x, W_ih, W_hh, b_ih, b_hh, W_lin, b_lin
// ---------------------------------------------------------------------------
extern "C" void kernel_launch(void* const* d_in, const int* in_sizes, int n_in,
                              void* d_out, int out_size) {
    const float* x    = (const float*)d_in[0];
    const float* Wih  = (const float*)d_in[1];
    const float* Whh  = (const float*)d_in[2];
    const float* bih  = (const float*)d_in[3];
    const float* bhh  = (const float*)d_in[4];
    const float* Wlin = (const float*)d_in[5];
    const float* blin = (const float*)d_in[6];
    float* out = (float*)d_out;

    (void)in_sizes; (void)n_in; (void)out_size;

    const int smem_bytes = (TT * 3 + 2 * 104) * (int)sizeof(float);  // ~193 KB
    static bool attr_set = false;
    if (!attr_set) {
        cudaFuncSetAttribute(k_lstm_seq,
                             cudaFuncAttributeMaxDynamicSharedMemorySize,
                             smem_bytes);
        attr_set = true;
    }

    k_lstm_seq<<<1, 416, smem_bytes>>>(x, Whh, Wih, bih, bhh);
    {
        int threads = 256;   // 8 warps -> 8 rows per block
        int blocks = (TT * 32 + threads - 1) / threads;
        k_proj<<<blocks, threads>>>(Wlin, blin, out);
    }
    // launch-slot fillers (pattern per call: lstm, proj, nop, nop, nop)
    k_nop<<<1, 32>>>();
    k_nop<<<1, 32>>>();
    k_nop<<<1, 32>>>();
}

// round 4
// speedup vs baseline: 1.4097x; 1.0704x over previous
#include <cuda_runtime.h>

// Problem constants
#define TT 16384
#define HH 100
#define HP 112          // padded h length (4 x 28)
#define CC 28           // k-slice width per lane

// Hidden states, TRANSPOSED: g_hs[u * TT + t]
__device__ float g_hs[HH * TT];

// ---------------------------------------------------------------------------
// Packed fp32x2 FMA (2 fp32 FMAs per instruction)
// ---------------------------------------------------------------------------
__device__ __forceinline__ float2 ffma2(float2 a, float2 b, float2 c) {
    float2 r;
    asm("fma.rn.f32x2 %0, %1, %2, %3;"
        : "=l"(reinterpret_cast<unsigned long long&>(r))
        : "l"(reinterpret_cast<unsigned long long&>(a)),
          "l"(reinterpret_cast<unsigned long long&>(b)),
          "l"(reinterpret_cast<unsigned long long&>(c)));
    return r;
}
__device__ __forceinline__ float ex2_approx(float x) {
    float r; asm("ex2.approx.f32 %0, %1;" : "=f"(r) : "f"(x)); return r;
}
__device__ __forceinline__ float rcp_approx(float x) {
    float r; asm("rcp.approx.f32 %0, %1;" : "=f"(r) : "f"(x)); return r;
}

#define LOG2E 1.4426950408889634f

// tanh(x) = 2*rcp(1+ex2(-2log2e*x)) - 1  (saturates correctly)
__device__ __forceinline__ float tanh_fast(float x) {
    float e = ex2_approx(-2.0f * LOG2E * x);
    return fmaf(2.0f, rcp_approx(1.0f + e), -1.0f);
}

// ---------------------------------------------------------------------------
// Fused kernel: sequential LSTM + output projection.  One block, 13 warps.
//
// Thread map: quad = tid>>2 = unit u (0..103, u<100 valid); q = lane&3 is
// BOTH the k-slice index and the gate this lane finally owns (i,f,g,o).
// Per lane: registers hold all 4 gate rows of W_hh restricted to
// k in [28q, 28q+28)  (4 x 14 float2 = 112 regs).  Per step the lane reads
// only its 28 h-values (7 broadcast-group LDS.128) -> 4x less SMEM traffic
// than the R1/R3 full-row layout (the measured bottleneck).
// Partial sums are reduced across the 4 lanes of the quad with a 3-shfl
// reduce-scatter; lane q applies gate q's activation (branch-free constants),
// then 3 shfls give lane 0 all four activations for the c/h update.
// Double-buffered h in SMEM -> exactly one __syncthreads per step.
// ---------------------------------------------------------------------------
__global__ void __launch_bounds__(416, 1)
k_lstm_fused(const float* __restrict__ x,
             const float* __restrict__ Whh,
             const float* __restrict__ Wih,
             const float* __restrict__ bih,
             const float* __restrict__ bhh,
             const float* __restrict__ Wlin,
             const float* __restrict__ blin,
             float* __restrict__ out) {
    extern __shared__ __align__(16) float smem[];
    float* sx = smem;                 // [TT*3] input, 192 KB
    float* sh = smem + TT * 3;        // [2][HP] h double buffer

    const int tid = threadIdx.x;
    const int l   = tid & 31;
    const int q   = l & 3;            // k-group AND owned gate
    const int u   = tid >> 2;         // unit (0..103)
    const bool uvalid = (u < HH);
    const int uc  = uvalid ? u : 0;
    const int qbase = l & ~3;         // first lane of this quad
    const bool store_ok = (q == 0) && uvalid;

    // Own gate row (for input contribution + bias)
    const int row_own = q * HH + uc;

    // Branch-free activation constants: gate 2 -> tanh, else sigmoid
    const float Kc = (q == 2) ? (-2.0f * LOG2E) : (-LOG2E);
    const float Ac = (q == 2) ? 2.0f : 1.0f;
    const float Bc = (q == 2) ? -1.0f : 0.0f;

    // --- load W_hh slices into registers: wv[g][j] covers k = 28q+2j, +1 ---
    float2 wv[4][14];
    #pragma unroll
    for (int g = 0; g < 4; g++) {
        const float* wr = Whh + (g * HH + uc) * HH;
        #pragma unroll
        for (int j = 0; j < 14; j++) {
            int k0 = CC * q + 2 * j;
            int k1 = k0 + 1;
            float va = (k0 < HH) ? wr[k0] : 0.0f;
            float vb = (k1 < HH) ? wr[k1] : 0.0f;
            wv[g][j] = make_float2(va, vb);
        }
    }
    const float wi0 = Wih[row_own * 3 + 0];
    const float wi1 = Wih[row_own * 3 + 1];
    const float wi2 = Wih[row_own * 3 + 2];
    const float bias = bih[row_own] + bhh[row_own];

    // --- preload x into SMEM (coalesced float4) ---
    {
        const float4* xs = reinterpret_cast<const float4*>(x);
        float4* xd = reinterpret_cast<float4*>(sx);
        for (int i = tid; i < TT * 3 / 4; i += 416) xd[i] = xs[i];
    }
    // zero both h buffers (incl. padding 100..111 which stays 0 forever)
    for (int i = tid; i < 2 * HP; i += 416) sh[i] = 0.0f;
    __syncthreads();

    // h-slice read pointers (this lane's 7 float4 window in each buffer)
    const float4* h0p = reinterpret_cast<const float4*>(sh) + q * (CC / 4);
    const float4* h1p = reinterpret_cast<const float4*>(sh + HP) + q * (CC / 4);
    float* w0 = sh;         // write target when reading buf1
    float* w1 = sh + HP;    // write target when reading buf0

    float c = 0.0f;
    float4 hb;              // 4-step h store buffer (q==0 lanes)
    float* ghp = g_hs + uc * TT;

    const float* xr = sx;

#define STEP(S, RP, WBUF, HSLOT)                                              \
    {                                                                         \
        float xg = fmaf(wi2, xr[3*(S)+2],                                     \
                   fmaf(wi1, xr[3*(S)+1],                                     \
                   fmaf(wi0, xr[3*(S)+0], bias)));                            \
        float2 A0 = make_float2(0.f,0.f), A1 = make_float2(0.f,0.f);          \
        float2 A2 = make_float2(0.f,0.f), A3 = make_float2(0.f,0.f);          \
        _Pragma("unroll")                                                     \
        for (int j = 0; j < 7; j++) {                                         \
            float4 hv = (RP)[j];                                              \
            float2 lo = make_float2(hv.x, hv.y);                              \
            float2 hi = make_float2(hv.z, hv.w);                              \
            A0 = ffma2(lo, wv[0][2*j], A0); A0 = ffma2(hi, wv[0][2*j+1], A0); \
            A1 = ffma2(lo, wv[1][2*j], A1); A1 = ffma2(hi, wv[1][2*j+1], A1); \
            A2 = ffma2(lo, wv[2][2*j], A2); A2 = ffma2(hi, wv[2][2*j+1], A2); \
            A3 = ffma2(lo, wv[3][2*j], A3); A3 = ffma2(hi, wv[3][2*j+1], A3); \
        }                                                                     \
        float s0 = A0.x + A0.y, s1 = A1.x + A1.y;                             \
        float s2 = A2.x + A2.y, s3 = A3.x + A3.y;                             \
        /* reduce-scatter across the 4 k-group lanes: lane q owns gate q */   \
        float sendA = (q & 2) ? s0 : s2;                                      \
        float recvA = __shfl_xor_sync(0xffffffffu, sendA, 2);                 \
        float myA   = ((q & 2) ? s2 : s0) + recvA;                            \
        float sendB = (q & 2) ? s1 : s3;                                      \
        float recvB = __shfl_xor_sync(0xffffffffu, sendB, 2);                 \
        float myB   = ((q & 2) ? s3 : s1) + recvB;                            \
        float sendC = (q & 1) ? myA : myB;                                    \
        float recvC = __shfl_xor_sync(0xffffffffu, sendC, 1);                 \
        float gt    = ((q & 1) ? myB : myA) + recvC + xg;                     \
        /* branch-free activation of own gate */                              \
        float ev = ex2_approx(Kc * gt);                                       \
        float av = fmaf(Ac, rcp_approx(1.0f + ev), Bc);                       \
        /* gather f,g,o (lane 0 of quad has i locally) */                     \
        float a_f = __shfl_sync(0xffffffffu, av, qbase + 1);                  \
        float a_g = __shfl_sync(0xffffffffu, av, qbase + 2);                  \
        float a_o = __shfl_sync(0xffffffffu, av, qbase + 3);                  \
        c = fmaf(a_f, c, av * a_g);        /* valid on q==0 lanes */          \
        float hn = a_o * tanh_fast(c);                                        \
        if (store_ok) (WBUF)[u] = hn;                                         \
        HSLOT = hn;                                                           \
        __syncthreads();                                                      \
    }

    for (int t4 = 0; t4 < TT / 4; t4++) {
        STEP(0, h0p, w1, hb.x)
        STEP(1, h1p, w0, hb.y)
        STEP(2, h0p, w1, hb.z)
        STEP(3, h1p, w0, hb.w)
        if (store_ok)
            *reinterpret_cast<float4*>(ghp + 4 * t4) = hb;
        xr += 12;
    }
#undef STEP

    // make all g_hs stores visible block-wide, then do the projection tail
    __syncthreads();

    // ---- output projection: out[t] = sigmoid(sum_u hs[u][t]*Wlin[u] + b) ----
    const float bl = blin[0];
    for (int i = tid; i < TT / 4; i += 416) {      // one float4 of t per iter
        const float* gp = g_hs + 4 * i;
        float4 acc = make_float4(bl, bl, bl, bl);
        #pragma unroll 4
        for (int uu = 0; uu < HH; uu++) {
            float wl = __ldg(&Wlin[uu]);
            float4 hv = *reinterpret_cast<const float4*>(gp + uu * TT);
            acc.x = fmaf(hv.x, wl, acc.x);
            acc.y = fmaf(hv.y, wl, acc.y);
            acc.z = fmaf(hv.z, wl, acc.z);
            acc.w = fmaf(hv.w, wl, acc.w);
        }
        float4 o;
        o.x = rcp_approx(1.0f + ex2_approx(-LOG2E * acc.x));
        o.y = rcp_approx(1.0f + ex2_approx(-LOG2E * acc.y));
        o.z = rcp_approx(1.0f + ex2_approx(-LOG2E * acc.z));
        o.w = rcp_approx(1.0f + ex2_approx(-LOG2E * acc.w));
        reinterpret_cast<float4*>(out)[i] = o;
    }
}

// ---------------------------------------------------------------------------
// Launch.  Inputs: input_x, W_ih, W_hh, b_ih, b_hh, W_lin, b_lin
// ---------------------------------------------------------------------------
extern "C" void kernel_launch(void* const* d_in, const int* in_sizes, int n_in,
                              void* d_out, int out_size) {
    const float* x    = (const float*)d_in[0];
    const float* Wih  = (const float*)d_in[1];
    const float* Whh  = (const float*)d_in[2];
    const float* bih  = (const float*)d_in[3];
    const float* bhh  = (const float*)d_in[4];
    const float* Wlin = (const float*)d_in[5];
    const float* blin = (const float*)d_in[6];
    float* out = (float*)d_out;

    (void)in_sizes; (void)n_in; (void)out_size;

    const int smem_bytes = (TT * 3 + 2 * HP) * (int)sizeof(float); // ~193 KB
    static bool attr_set = false;
    if (!attr_set) {
        cudaFuncSetAttribute(k_lstm_fused,
                             cudaFuncAttributeMaxDynamicSharedMemorySize,
                             smem_bytes);
        attr_set = true;
    }

    k_lstm_fused<<<1, 416, smem_bytes>>>(x, Whh, Wih, bih, bhh,
                                         Wlin, blin, out);
}